// round 17
// baseline (speedup 1.0000x reference)
#include <cuda_runtime.h>
#include <cuda_fp16.h>
#include <cstdint>
#include <math.h>

#define B_  4
#define H_  16
#define N_  2048
#define Dh_ 64
#define DIM_ 1024
#define M_  (B_*N_)          // 8192
#define ELEMS (B_*H_*N_*Dh_) // 8388608
#define NCTA 296

// fp16 fragment-packed operands (u32 = half2 along k)
__device__ __align__(16) __half g_xph[M_ * DIM_];
__device__ __align__(16) __half g_wqph[DIM_ * DIM_];
__device__ __align__(16) __half g_wkvph[DIM_ * 2 * DIM_];
__device__ __align__(16) __half g_woph[DIM_ * DIM_];
__device__ __align__(16) __half g_qph[ELEMS];
__device__ __align__(16) __half g_kph[ELEMS];
__device__ __align__(16) __half g_vph[ELEMS];
__device__ __align__(16) __half g_oph[ELEMS];

__device__ __forceinline__ uint32_t h2u(float a, float b) {
    __half2 h = __floats2half2_rn(a, b);
    return *reinterpret_cast<uint32_t*>(&h);
}
__device__ __forceinline__ uint32_t smem_u32(const void* p) {
    uint32_t a;
    asm("{ .reg .u64 t; cvta.to.shared.u64 t, %1; cvt.u32.u64 %0, t; }"
        : "=r"(a) : "l"(p));
    return a;
}

#define MMA_F16(c, a, b0v, b1v) \
    asm volatile("mma.sync.aligned.m16n8k16.row.col.f32.f16.f16.f32 " \
        "{%0,%1,%2,%3},{%4,%5,%6,%7},{%8,%9},{%0,%1,%2,%3};" \
        : "+f"((c)[0]), "+f"((c)[1]), "+f"((c)[2]), "+f"((c)[3]) \
        : "r"((a)[0]), "r"((a)[1]), "r"((a)[2]), "r"((a)[3]), \
          "r"(b0v), "r"(b1v))

// ---------------------------------------------------------------------------
// Fused pack kernel (verbatim R15/R16).
// ---------------------------------------------------------------------------
__global__ void __launch_bounds__(256) pack_all_k(
    const float* __restrict__ x, const float* __restrict__ Wq,
    const float* __restrict__ Wkv, const float* __restrict__ Wo)
{
    const int bb = blockIdx.x;
    if (bb < 4096) {
        const int t = bb * 256 + threadIdx.x;
        const int lane = t & 31, grp = (t >> 5) & 7;
        const int ktile = (t >> 8) & 63, mtile = t >> 14;
        const int l4 = lane >> 2, lk = lane & 3;
        const int r = mtile * 128 + grp * 16 + l4;
        const int kb = ktile * 16 + 2 * lk;
        const float* x0 = x + (size_t)r * DIM_ + kb;
        const float* x1 = x + (size_t)(r + 8) * DIM_ + kb;
        uint4 v;
        v.x = h2u(x0[0], x0[1]);
        v.y = h2u(x1[0], x1[1]);
        v.z = h2u(x0[8], x0[9]);
        v.w = h2u(x1[8], x1[9]);
        reinterpret_cast<uint4*>(g_xph)[t] = v;
    } else {
        const float* W;
        __half* dst;
        int Nc, t;
        if (bb < 4608)      { W = Wq;  dst = g_wqph;  Nc = DIM_;     t = (bb - 4096) * 256 + threadIdx.x; }
        else if (bb < 5632) { W = Wkv; dst = g_wkvph; Nc = 2 * DIM_; t = (bb - 4608) * 256 + threadIdx.x; }
        else                { W = Wo;  dst = g_woph;  Nc = DIM_;     t = (bb - 5632) * 256 + threadIdx.x; }
        const int lane = t & 31, pair = (t >> 5) & 7;
        const int ktile = (t >> 8) & 63, ntile = t >> 14;
        const int l4 = lane >> 2, lk = lane & 3;
        const int k = ktile * 16 + 2 * lk;
        const int c = ntile * 128 + pair * 16 + l4;
        uint4 v;
        v.x = h2u(W[(size_t)k * Nc + c],           W[(size_t)(k + 1) * Nc + c]);
        v.y = h2u(W[(size_t)(k + 8) * Nc + c],     W[(size_t)(k + 9) * Nc + c]);
        v.z = h2u(W[(size_t)k * Nc + c + 8],       W[(size_t)(k + 1) * Nc + c + 8]);
        v.w = h2u(W[(size_t)(k + 8) * Nc + c + 8], W[(size_t)(k + 9) * Nc + c + 8]);
        reinterpret_cast<uint4*>(dst)[t] = v;
    }
}

// ---------------------------------------------------------------------------
// fp16 GEMM core v2: BM=256, BN=128, BK=64, 8 warps (4M x 2N), warp 64x64.
// Stage = A 2048 u4 (two mtile128 blocks) + B 1024 u4 = 48KB; 3 stages.
// Per kt per warp: 4 A-LDS.128 + 4 B-LDS.128 -> 32 MMAs (128 B/MMA).
// ---------------------------------------------------------------------------
#define G2_STGU4 3072
#define G2_SMEM (3 * G2_STGU4 * 16)   // 147456 B

template<typename EPI>
__device__ __forceinline__ void gemm_core2(
    const uint4* __restrict__ Ap, const uint4* __restrict__ Bp,
    int mt2, int ntile, uint4* gsm4, EPI epi)
{
    const int tid = threadIdx.x;
    const int wid = tid >> 5, lane = tid & 31;
    const uint32_t smb = smem_u32(gsm4);

    __syncthreads();   // previous tile's smem reads complete

    float acc[4][8][4];
    #pragma unroll
    for (int f = 0; f < 4; f++)
        #pragma unroll
        for (int g = 0; g < 8; g++)
            #pragma unroll
            for (int i = 0; i < 4; i++) acc[f][g][i] = 0.f;

    auto load_stage = [&](int t, int s) {
        const uint32_t abase = smb + (uint32_t)(s * G2_STGU4) * 16;
        const uint32_t bbase = abase + 2048 * 16;
        const uint4* asrc0 = Ap + ((size_t)((mt2 * 2) * 64 + 4 * t)) * 256;
        const uint4* asrc1 = Ap + ((size_t)((mt2 * 2 + 1) * 64 + 4 * t)) * 256;
        const uint4* bsrc  = Bp + ((size_t)(ntile * 64 + 4 * t)) * 256;
        #pragma unroll
        for (int i = 0; i < 4; i++) {
            const int off = tid + i * 256;
            asm volatile("cp.async.cg.shared.global [%0], [%1], 16;"
                         :: "r"(abase + (uint32_t)off * 16), "l"(asrc0 + off));
            asm volatile("cp.async.cg.shared.global [%0], [%1], 16;"
                         :: "r"(abase + 1024 * 16 + (uint32_t)off * 16), "l"(asrc1 + off));
            asm volatile("cp.async.cg.shared.global [%0], [%1], 16;"
                         :: "r"(bbase + (uint32_t)off * 16), "l"(bsrc + off));
        }
        asm volatile("cp.async.commit_group;" ::: "memory");
    };

    load_stage(0, 0);
    load_stage(1, 1);

    const int wm = wid & 3, wn = wid >> 2;
    const int mh = wm >> 1;
    const int gbase = (wm & 1) * 4;
    const int b_pair0 = wn * 4;

    int sidx = 0;
    for (int t = 0; t < 16; t++) {
        asm volatile("cp.async.wait_group 1;" ::: "memory");
        __syncthreads();

        if (t + 2 < 16) {
            int s2 = sidx + 2; if (s2 >= 3) s2 -= 3;
            load_stage(t + 2, s2);
        } else {
            asm volatile("cp.async.commit_group;" ::: "memory");
        }

        const uint4* As_ = gsm4 + sidx * G2_STGU4 + mh * 1024;
        const uint4* Bs_ = gsm4 + sidx * G2_STGU4 + 2048;
        #pragma unroll
        for (int kt = 0; kt < 4; kt++) {
            uint32_t af[4][4];
            #pragma unroll
            for (int f = 0; f < 4; f++) {
                uint4 a4 = As_[(kt * 8 + gbase + f) * 32 + lane];
                af[f][0] = a4.x; af[f][1] = a4.y; af[f][2] = a4.z; af[f][3] = a4.w;
            }
            #pragma unroll
            for (int pl = 0; pl < 4; pl++) {
                uint4 b4 = Bs_[(kt * 8 + b_pair0 + pl) * 32 + lane];
                #pragma unroll
                for (int f = 0; f < 4; f++) {
                    MMA_F16(acc[f][2 * pl],     af[f], b4.x, b4.y);
                    MMA_F16(acc[f][2 * pl + 1], af[f], b4.z, b4.w);
                }
            }
        }
        if (++sidx >= 3) sidx -= 3;
    }
    epi(acc);
}

// ---------------------------------------------------------------------------
// Merged projection GEMM (Q + KV), persistent over 768 tiles (32 mt2 x 24 nt).
// ---------------------------------------------------------------------------
__global__ void __launch_bounds__(256, 1) proj_k()
{
    extern __shared__ __align__(16) uint4 gsm4[];
    const int tid = threadIdx.x;
    const int wid = tid >> 5, lane = tid & 31;
    const int wm = wid & 3, wn = wid >> 2;
    const int l4 = lane >> 2, lk = lane & 3;

    for (int tile = blockIdx.x; tile < 32 * 24; tile += gridDim.x) {
        const int mt2 = tile / 24;
        const int ntile = tile % 24;
        const bool isq = ntile < 8;
        const int nb = isq ? ntile : ntile - 8;
        const int m0 = mt2 * 256;
        const int n0 = nb * 128;

        gemm_core2((const uint4*)g_xph,
                   isq ? (const uint4*)g_wqph : (const uint4*)g_wkvph,
                   mt2, nb, gsm4,
            [&](float (&acc)[4][8][4]) {
                const int r0 = m0 + wm * 64 + l4;
                const int c0 = n0 + wn * 64 + lk * 2;
                #pragma unroll
                for (int f = 0; f < 4; f++) {
                    #pragma unroll
                    for (int g = 0; g < 8; g++) {
                        const int n = c0 + g * 8;
                        #pragma unroll
                        for (int half_ = 0; half_ < 2; half_++) {
                            const int m = r0 + f * 16 + half_ * 8;
                            const float vx = acc[f][g][half_ * 2 + 0];
                            const float vy = acc[f][g][half_ * 2 + 1];
                            const int b = m >> 11, nn = m & 2047;
                            if (isq) {
                                const int bh = (b << 4) + (n >> 6);
                                const int d = n & 63;
                                const int rowgrp = nn >> 4, l4q = nn & 7, rh = (nn >> 3) & 1;
                                const int kt = d >> 4, cc = d & 15;
                                const int lkq = (cc & 7) >> 1, hi = (cc >> 3) & 1;
                                const size_t idx = ((size_t)(bh * 128 + rowgrp) * 4 + kt) * 128
                                                 + (l4q * 4 + lkq) * 4 + rh + 2 * hi;
                                reinterpret_cast<uint32_t*>(g_qph)[idx] =
                                    h2u(vx * 0.125f, vy * 0.125f);
                            } else {
                                const int cfull = n & 1023;
                                const int h = cfull >> 6, d = cfull & 63;
                                const int bh = (b << 4) + h;
                                const int tile64 = nn >> 6, ctok = nn & 63;
                                if (n < 1024) {
                                    const int pair = ctok >> 4, l4b = ctok & 7, gsub = (ctok >> 3) & 1;
                                    const int kt = d >> 4, cc = d & 15;
                                    const int lkk = (cc & 7) >> 1, khi = (cc >> 3) & 1;
                                    const size_t idx = ((size_t)(bh * 32 + tile64) * 16 + kt * 4 + pair) * 128
                                                     + (l4b * 4 + lkk) * 4 + gsub * 2 + khi;
                                    reinterpret_cast<uint32_t*>(g_kph)[idx] = h2u(vx, vy);
                                } else {
                                    const int ktok = ctok >> 4, cct = ctok & 15;
                                    const int lkt = (cct & 7) >> 1, khit = (cct >> 3) & 1;
                                    const int hpos = ctok & 1;
                                    #pragma unroll
                                    for (int e = 0; e < 2; e++) {
                                        const int dd = d + e;
                                        const int pairv = dd >> 4, l4v = dd & 7, gsv = (dd >> 3) & 1;
                                        const size_t idx = ((size_t)(bh * 32 + tile64) * 16 + ktok * 4 + pairv) * 128
                                                         + (l4v * 4 + lkt) * 4 + gsv * 2 + khit;
                                        g_vph[idx * 2 + hpos] = __float2half_rn(e ? vy : vx);
                                    }
                                }
                            }
                        }
                    }
                }
            });
    }
}

// ---------------------------------------------------------------------------
// Output GEMM, persistent over 256 tiles (32 mt2 x 8 nt).
// ---------------------------------------------------------------------------
__global__ void __launch_bounds__(256, 1)
outg_k(float* __restrict__ Cout, const float* __restrict__ bias)
{
    extern __shared__ __align__(16) uint4 gsm4[];
    const int tid = threadIdx.x;
    const int wid = tid >> 5, lane = tid & 31;
    const int wm = wid & 3, wn = wid >> 2;
    const int l4 = lane >> 2, lk = lane & 3;

    for (int tile = blockIdx.x; tile < 32 * 8; tile += gridDim.x) {
        const int mt2 = tile >> 3;
        const int ntile = tile & 7;
        const int m0 = mt2 * 256, n0 = ntile * 128;

        gemm_core2((const uint4*)g_oph, (const uint4*)g_woph, mt2, ntile, gsm4,
            [&](float (&acc)[4][8][4]) {
                const int r0 = m0 + wm * 64 + l4;
                const int c0 = n0 + wn * 64 + lk * 2;
                #pragma unroll
                for (int f = 0; f < 4; f++) {
                    #pragma unroll
                    for (int g = 0; g < 8; g++) {
                        const int n = c0 + g * 8;
                        #pragma unroll
                        for (int half_ = 0; half_ < 2; half_++) {
                            const int m = r0 + f * 16 + half_ * 8;
                            float2 v;
                            v.x = acc[f][g][half_ * 2 + 0] + bias[n];
                            v.y = acc[f][g][half_ * 2 + 1] + bias[n + 1];
                            *(float2*)&Cout[(size_t)m * DIM_ + n] = v;
                        }
                    }
                }
            });
    }
}

// ---------------------------------------------------------------------------
// Flash attention fp16, persistent (verbatim R16).
// ---------------------------------------------------------------------------
#define FL_BYTES (2048 * 16)   // 32768

__global__ void __launch_bounds__(256, 2) flash2_k()
{
    extern __shared__ __align__(16) uint4 smv4[];
    const int tid = threadIdx.x;
    const int wid = tid >> 5, lane = tid & 31;
    const int l4 = lane >> 2, lk = lane & 3;
    const uint32_t smb = smem_u32(smv4);

    for (int w = blockIdx.x; w < 1024; w += gridDim.x) {
        const int rb = 15 - (w >> 6);
        const int bh = w & 63;
        const int m0 = rb * 128;
        const int R0 = m0 + wid * 16;

        asm volatile("cp.async.wait_group 0;" ::: "memory");
        __syncthreads();

        uint32_t aq[4][4];
        {
            const uint4* qsrc = (const uint4*)g_qph + ((size_t)(bh * 128 + (R0 >> 4))) * 128;
            #pragma unroll
            for (int kt = 0; kt < 4; kt++) {
                uint4 a4 = qsrc[kt * 32 + lane];
                aq[kt][0] = a4.x; aq[kt][1] = a4.y; aq[kt][2] = a4.z; aq[kt][3] = a4.w;
            }
        }

        float o[8][4];
        #pragma unroll
        for (int dg = 0; dg < 8; dg++)
            #pragma unroll
            for (int i = 0; i < 4; i++) o[dg][i] = 0.f;
        float mr0 = -1e30f, mr1 = -1e30f, lr0 = 0.f, lr1 = 0.f;

        const int ntiles = 2 * rb + 2;

        auto load_tile = [&](int t, int s) {
            const uint4* ksrc = (const uint4*)g_kph + ((size_t)(bh * 32 + t)) * 512;
            const uint4* vsrc = (const uint4*)g_vph + ((size_t)(bh * 32 + t)) * 512;
            const uint32_t kd = smb + (uint32_t)(s * 512) * 16;
            const uint32_t vd = smb + (uint32_t)(1024 + s * 512) * 16;
            #pragma unroll
            for (int i = 0; i < 2; i++) {
                const int off = tid + i * 256;
                asm volatile("cp.async.cg.shared.global [%0], [%1], 16;"
                             :: "r"(kd + (uint32_t)off * 16), "l"(ksrc + off));
                asm volatile("cp.async.cg.shared.global [%0], [%1], 16;"
                             :: "r"(vd + (uint32_t)off * 16), "l"(vsrc + off));
            }
        };

        load_tile(0, 0);
        asm volatile("cp.async.commit_group;" ::: "memory");
        load_tile(1, 1);
        asm volatile("cp.async.commit_group;" ::: "memory");

        const int row0 = R0 + l4;
        const int row1 = R0 + l4 + 8;

        for (int t = 0; t < ntiles; t++) {
            const int s = t & 1;
            asm volatile("cp.async.wait_group 1;" ::: "memory");
            __syncthreads();

            if (t * 64 <= R0 + 15) {
                const uint4* Ksm = smv4 + s * 512;
                const uint4* Vsm = smv4 + 1024 + s * 512;
                #pragma unroll
                for (int jc = 0; jc < 2; jc++) {
                    const int j0c = t * 64 + jc * 32;
                    if (j0c > R0 + 15) break;

                    float s4[4][4];
                    #pragma unroll
                    for (int jg = 0; jg < 4; jg++)
                        #pragma unroll
                        for (int i = 0; i < 4; i++) s4[jg][i] = 0.f;
                    #pragma unroll
                    for (int kt = 0; kt < 4; kt++) {
                        #pragma unroll
                        for (int pr = 0; pr < 2; pr++) {
                            uint4 b4 = Ksm[(kt * 4 + jc * 2 + pr) * 32 + lane];
                            MMA_F16(s4[2 * pr],     aq[kt], b4.x, b4.y);
                            MMA_F16(s4[2 * pr + 1], aq[kt], b4.z, b4.w);
                        }
                    }

                    if (j0c + 31 > R0) {
                        #pragma unroll
                        for (int jg = 0; jg < 4; jg++) {
                            const int jb = j0c + jg * 8 + 2 * lk;
                            if (jb     > row0) s4[jg][0] = -1e30f;
                            if (jb + 1 > row0) s4[jg][1] = -1e30f;
                            if (jb     > row1) s4[jg][2] = -1e30f;
                            if (jb + 1 > row1) s4[jg][3] = -1e30f;
                        }
                    }

                    float mx0 = -1e30f, mx1 = -1e30f;
                    #pragma unroll
                    for (int jg = 0; jg < 4; jg++) {
                        mx0 = fmaxf(mx0, fmaxf(s4[jg][0], s4[jg][1]));
                        mx1 = fmaxf(mx1, fmaxf(s4[jg][2], s4[jg][3]));
                    }
                    mx0 = fmaxf(mx0, __shfl_xor_sync(0xffffffffu, mx0, 1));
                    mx0 = fmaxf(mx0, __shfl_xor_sync(0xffffffffu, mx0, 2));
                    mx1 = fmaxf(mx1, __shfl_xor_sync(0xffffffffu, mx1, 1));
                    mx1 = fmaxf(mx1, __shfl_xor_sync(0xffffffffu, mx1, 2));

                    const float mn0 = fmaxf(mr0, mx0);
                    const float mn1 = fmaxf(mr1, mx1);
                    const float a0 = __expf(mr0 - mn0);
                    const float a1 = __expf(mr1 - mn1);
                    mr0 = mn0; mr1 = mn1;

                    float sum0 = 0.f, sum1 = 0.f;
                    float p[4][4];
                    #pragma unroll
                    for (int jg = 0; jg < 4; jg++) {
                        p[jg][0] = __expf(s4[jg][0] - mn0);
                        p[jg][1] = __expf(s4[jg][1] - mn0);
                        p[jg][2] = __expf(s4[jg][2] - mn1);
                        p[jg][3] = __expf(s4[jg][3] - mn1);
                        sum0 += p[jg][0] + p[jg][1];
                        sum1 += p[jg][2] + p[jg][3];
                    }
                    sum0 += __shfl_xor_sync(0xffffffffu, sum0, 1);
                    sum0 += __shfl_xor_sync(0xffffffffu, sum0, 2);
                    sum1 += __shfl_xor_sync(0xffffffffu, sum1, 1);
                    sum1 += __shfl_xor_sync(0xffffffffu, sum1, 2);
                    lr0 = lr0 * a0 + sum0;
                    lr1 = lr1 * a1 + sum1;

                    #pragma unroll
                    for (int dg = 0; dg < 8; dg++) {
                        o[dg][0] *= a0; o[dg][1] *= a0;
                        o[dg][2] *= a1; o[dg][3] *= a1;
                    }

                    uint32_t pa[2][4];
                    #pragma unroll
                    for (int kc = 0; kc < 2; kc++) {
                        pa[kc][0] = h2u(p[2 * kc][0],     p[2 * kc][1]);
                        pa[kc][1] = h2u(p[2 * kc][2],     p[2 * kc][3]);
                        pa[kc][2] = h2u(p[2 * kc + 1][0], p[2 * kc + 1][1]);
                        pa[kc][3] = h2u(p[2 * kc + 1][2], p[2 * kc + 1][3]);
                    }

                    #pragma unroll
                    for (int kc = 0; kc < 2; kc++) {
                        #pragma unroll
                        for (int pd = 0; pd < 4; pd++) {
                            uint4 b4 = Vsm[((jc * 2 + kc) * 4 + pd) * 32 + lane];
                            MMA_F16(o[2 * pd],     pa[kc], b4.x, b4.y);
                            MMA_F16(o[2 * pd + 1], pa[kc], b4.z, b4.w);
                        }
                    }
                }
            }
            __syncthreads();
            if (t + 2 < ntiles) load_tile(t + 2, s);
            asm volatile("cp.async.commit_group;" ::: "memory");
        }

        const float inv0 = 1.0f / lr0;
        const float inv1 = 1.0f / lr1;
        const int bq = bh >> 4, hq = bh & 15;
        #pragma unroll
        for (int dg = 0; dg < 8; dg++) {
            #pragma unroll
            for (int half_ = 0; half_ < 2; half_++) {
                const int row = half_ ? row1 : row0;
                const int m = (bq << 11) + row;
                const float v0 = (half_ ? o[dg][2] * inv1 : o[dg][0] * inv0);
                const float v1 = (half_ ? o[dg][3] * inv1 : o[dg][1] * inv0);
                const int col = dg * 8 + 2 * lk;
                const int k = (hq << 6) + col;
                const int mt = m >> 7, grp = (m >> 4) & 7, l4m = m & 7, rh = (m >> 3) & 1;
                const int kt = k >> 4, cc = k & 15;
                const int lkk = (cc & 7) >> 1, hi = (cc >> 3) & 1;
                const size_t idx = ((size_t)(mt * 64 + kt) * 8 + grp) * 128
                                 + (l4m * 4 + lkk) * 4 + rh + 2 * hi;
                reinterpret_cast<uint32_t*>(g_oph)[idx] = h2u(v0, v1);
            }
        }
    }
}

// ---------------------------------------------------------------------------
extern "C" void kernel_launch(void* const* d_in, const int* in_sizes, int n_in,
                              void* d_out, int out_size)
{
    const float* x   = (const float*)d_in[0];
    const float* Wq  = (const float*)d_in[1];
    const float* Wkv = (const float*)d_in[2];
    const float* Wo  = (const float*)d_in[3];
    const float* bo  = (const float*)d_in[4];
    float* out = (float*)d_out;

    static bool attr_done = false;
    if (!attr_done) {
        cudaFuncSetAttribute(proj_k,   cudaFuncAttributeMaxDynamicSharedMemorySize, G2_SMEM);
        cudaFuncSetAttribute(outg_k,   cudaFuncAttributeMaxDynamicSharedMemorySize, G2_SMEM);
        cudaFuncSetAttribute(flash2_k, cudaFuncAttributeMaxDynamicSharedMemorySize, FL_BYTES);
        attr_done = true;
    }

    dim3 blk(256);
    pack_all_k<<<6144, blk>>>(x, Wq, Wkv, Wo);
    proj_k<<<148, blk, G2_SMEM>>>();
    flash2_k<<<NCTA, blk, FL_BYTES>>>();
    outg_k<<<148, blk, G2_SMEM>>>(out, bo);
}